// round 15
// baseline (speedup 1.0000x reference)
#include <cuda_runtime.h>
#include <cuda_fp16.h>
#include <math.h>
#include <stdint.h>

#define HH      224
#define C_      192
#define NPIX    49
#define HEADS   6
#define NWIN    8192
#define ATT_W   14406
#define NTHR    384

// ---- smem byte layout (95.7 KB -> 2 CTAs/SM) ----
#define IMG_X   0          // x A-image (24576); VF_HI aliases after Q-GEMM
#define IMG_Y   24576      // y A-image (24576); CTX frags alias during attention
#define QF_HI   49152      // 24576
#define KF_HI   73728      // 21504
#define LOGMW_O 95232      // 49 floats (+pad)
#define GOFF_O  95440      // 49 ints
#define SMEM_BYTES 95648
#define VF_HI   0
#define CTX_OFF 24576

// weight images (f16 hi only) in mma-B-fragment order: [w][chunk][12288]
__device__ __align__(16) __half g_Bimg[4][3][12288];

// ---------------- helpers ----------------
__device__ __forceinline__ void mma16816(float* c, const uint32_t* a, uint32_t b0, uint32_t b1) {
    asm volatile("mma.sync.aligned.m16n8k16.row.col.f32.f16.f16.f32 "
        "{%0,%1,%2,%3}, {%4,%5,%6,%7}, {%8,%9}, {%0,%1,%2,%3};"
        : "+f"(c[0]), "+f"(c[1]), "+f"(c[2]), "+f"(c[3])
        : "r"(a[0]), "r"(a[1]), "r"(a[2]), "r"(a[3]), "r"(b0), "r"(b1));
}
__device__ __forceinline__ uint32_t cvt2(float a, float b) {
    __half2 h2 = __float22half2_rn(make_float2(a, b));
    return *(uint32_t*)&h2;
}

// ---------------- prep: weights -> f16 fragment-order images (hi only) ----------------
__global__ void prep_w(const float* __restrict__ Wq, const float* __restrict__ Wk,
                       const float* __restrict__ Wv, const float* __restrict__ Wo)
{
    int e = blockIdx.x * 256 + threadIdx.x;
    if (e >= 4 * 36864) return;
    int wsel = e / 36864, r = e % 36864;
    int k = r / 192, n = r % 192;
    const float* W = (wsel == 0) ? Wq : (wsel == 1) ? Wk : (wsel == 2) ? Wv : Wo;
    __half h = __float2half_rn(W[k * 192 + n]);
    int chunk = k >> 6, kk = k & 63;
    int kt = kk >> 4, kc = kk & 15;
    int khi = kc >> 3, t = (kc & 7) >> 1, half = kc & 1;
    int ntile = n >> 3, g = n & 7;
    int lane = g * 4 + t;
    int off = ((kt * 24 + ntile) * 32 + lane) * 4 + khi * 2 + half;
    g_Bimg[wsel][chunk][off] = h;
}

// stage A element pair (hi only) into fragment-order image at base
__device__ __forceinline__ void stage_hi(char* smem, int base, int p, int c, float a0, float a1)
{
    uint32_t hi = cvt2(a0, a1);
    int mt = p >> 4, rr = p & 15;
    int g = rr & 7, hi8 = rr >> 3;
    int kt = c >> 4, cc = c & 15;
    int khi = cc >> 3, t = (cc & 7) >> 1;
    int reg = hi8 + 2 * khi;
    int off = (((kt * 4 + mt) * 32 + g * 4 + t) * 8 + reg * 2) * 2;
    *(uint32_t*)(smem + base + off) = hi;
}

// ---- 12-warp GEMM, 1-pass, barrier-free: B fragments read directly via LDG (L1/L2-hot).
// mode: 0 = direct gmem out (O), 1 = Q frags (scaled), 2 = K frags, 3 = VF frags (V)
__device__ void run_gemm(char* smem, const __half* img, int a_base,
                         float* __restrict__ gout, const int* s_goff,
                         int tx, int mode)
{
    const int wid = tx >> 5, lane = tx & 31;
    const int mp = wid >= 6, jg = wid - 6 * mp;   // mp in {0,1}, jg in {0..5}
    const int g = lane >> 2, t = lane & 3;

    float c[2][4][4];
    #pragma unroll
    for (int m2 = 0; m2 < 2; m2++)
        #pragma unroll
        for (int jj = 0; jj < 4; jj++)
            #pragma unroll
            for (int i = 0; i < 4; i++) c[m2][jj][i] = 0.0f;

    const uint2* bp = (const uint2*)img;
    #pragma unroll
    for (int kt = 0; kt < 12; kt++) {
        uint4 ah0 = *(const uint4*)(smem + a_base + ((kt * 4 + 2 * mp)     * 32 + lane) * 16);
        uint4 ah1 = *(const uint4*)(smem + a_base + ((kt * 4 + 2 * mp + 1) * 32 + lane) * 16);
        const int bbase = (kt >> 2) * 3072 + ((kt & 3) * 24 + jg * 4) * 32 + lane;
        #pragma unroll
        for (int jj = 0; jj < 4; jj++) {
            uint2 b = __ldg(&bp[bbase + jj * 32]);
            mma16816(c[0][jj], (const uint32_t*)&ah0, b.x, b.y);
            mma16816(c[1][jj], (const uint32_t*)&ah1, b.x, b.y);
        }
    }

    if (mode == 0) {
        // O: store straight to gmem via per-row base offsets (roll-back == gather map)
        #pragma unroll
        for (int m2 = 0; m2 < 2; m2++) {
            const int mt = 2 * mp + m2;
            const int r0 = mt * 16 + g, r1 = r0 + 8;
            int o0 = (r0 < NPIX) ? s_goff[r0] : 0;
            int o1 = (r1 < NPIX) ? s_goff[r1] : 0;
            #pragma unroll
            for (int jj = 0; jj < 4; jj++) {
                int col = (jg * 4 + jj) * 8 + 2 * t;
                if (r0 < NPIX) *(float2*)(gout + o0 + col) = make_float2(c[m2][jj][0], c[m2][jj][1]);
                if (r1 < NPIX) *(float2*)(gout + o1 + col) = make_float2(c[m2][jj][2], c[m2][jj][3]);
            }
        }
    } else if (mode == 1) {
        // Q: scale -> A-fragment image. h = jg; kb in {0,1}.
        const float SCALE = 0.17677669529663687f;
        #pragma unroll
        for (int m2 = 0; m2 < 2; m2++) {
            const int mt = 2 * mp + m2;
            #pragma unroll
            for (int kb = 0; kb < 2; kb++) {
                uint32_t w0 = cvt2(c[m2][2*kb][0]*SCALE,   c[m2][2*kb][1]*SCALE);
                uint32_t w1 = cvt2(c[m2][2*kb][2]*SCALE,   c[m2][2*kb][3]*SCALE);
                uint32_t w2 = cvt2(c[m2][2*kb+1][0]*SCALE, c[m2][2*kb+1][1]*SCALE);
                uint32_t w3 = cvt2(c[m2][2*kb+1][2]*SCALE, c[m2][2*kb+1][3]*SCALE);
                int off = (((jg * 4 + mt) * 2 + kb) * 32 + lane) * 16;
                *(uint4*)(smem + QF_HI + off) = make_uint4(w0, w1, w2, w3);
            }
        }
    } else if (mode == 2) {
        // K -> B-fragment image. h = jg, kb = jj>>1, khi = jj&1. Guard nt=2mt+1<7.
        #pragma unroll
        for (int m2 = 0; m2 < 2; m2++) {
            const int mt = 2 * mp + m2;
            #pragma unroll
            for (int jj = 0; jj < 4; jj++) {
                int kb = jj >> 1, khi = jj & 1;
                uint32_t h0 = cvt2(c[m2][jj][0], c[m2][jj][1]);
                uint32_t h1 = cvt2(c[m2][jj][2], c[m2][jj][3]);
                int base0 = (((jg * 2 + kb) * 7 + 2 * mt) * 32 + lane) * 8 + khi * 4;
                *(uint32_t*)(smem + KF_HI + base0) = h0;
                if (2 * mt + 1 < 7)
                    *(uint32_t*)(smem + KF_HI + base0 + 256) = h1;
            }
        }
    } else {
        // V: direct B-fragment store. Lane pairing rows (g, g^1) via shfl_xor lane^4.
        const int even = !(g & 1);
        const int tt = g >> 1;
        #pragma unroll
        for (int m2 = 0; m2 < 2; m2++) {
            const int mt = 2 * mp + m2;
            #pragma unroll
            for (int jj = 0; jj < 4; jj++) {
                int col = (jg * 4 + jj) * 8 + 2 * t;
                float p0 = __shfl_xor_sync(0xffffffffu, c[m2][jj][0], 4);
                float p1 = __shfl_xor_sync(0xffffffffu, c[m2][jj][1], 4);
                float p2 = __shfl_xor_sync(0xffffffffu, c[m2][jj][2], 4);
                float p3 = __shfl_xor_sync(0xffffffffu, c[m2][jj][3], 4);
                int m0 = 16 * mt + (even ? g : g - 1);
                float va0 = even ? c[m2][jj][0] : p1;
                float vb0 = even ? p0 : c[m2][jj][1];
                float va1 = even ? c[m2][jj][2] : p3;
                float vb1 = even ? p2 : c[m2][jj][3];
                va0 = (m0     < NPIX) ? va0 : 0.0f;
                vb0 = (m0 + 1 < NPIX) ? vb0 : 0.0f;
                va1 = (m0 + 8 < NPIX) ? va1 : 0.0f;
                vb1 = (m0 + 9 < NPIX) ? vb1 : 0.0f;
                int ch = col + (even ? 0 : 1);
                uint32_t h0 = cvt2(va0, vb0);
                uint32_t h1 = cvt2(va1, vb1);
                int hh = ch >> 5, nt2 = (ch >> 3) & 3, gg = ch & 7;
                int id = ((hh * 4 + mt) * 4 + nt2) * 32 + gg * 4 + tt;
                *(uint2*)(smem + VF_HI + id * 8) = make_uint2(h0, h1);
            }
        }
    }
}

__global__ __launch_bounds__(NTHR, 2)
void fused_winattn(const float* __restrict__ x, const float* __restrict__ y,
                   float* __restrict__ out, float* __restrict__ att_out)
{
    extern __shared__ __align__(16) char smem[];
    float* s_logmw = (float*)(smem + LOGMW_O);
    int*   s_goff  = (int*)(smem + GOFF_O);

    const int tx = threadIdx.x;
    const int wid = tx >> 5, lane = tx & 31;
    const int w  = blockIdx.x;
    const int b  = w >> 10;
    const int wr = (w >> 5) & 31;
    const int wc = w & 31;

    // ---- gather x (roll + mask) AND y -> A-images; logmw, goff ----
    for (int p = wid; p < NPIX; p += 12) {
        int i = p / 7, j = p - i * 7;
        int hs = wr * 7 + i + 3;  if (hs >= HH) hs -= HH;
        int vs = wc * 7 + j + 3;  if (vs >= HH) vs -= HH;
        int goff = ((b * HH + hs) * HH + vs) * C_;
        float2 xv[3], yv[3];
        int cnt = 0;
        #pragma unroll
        for (int u = 0; u < 3; u++) {
            xv[u] = *(const float2*)(x + goff + 2 * lane + 64 * u);
            yv[u] = *(const float2*)(y + goff + 2 * lane + 64 * u);
            cnt += (xv[u].x > 0.95f ? 0 : 1) + (xv[u].y > 0.95f ? 0 : 1);
        }
        #pragma unroll
        for (int o = 16; o; o >>= 1) cnt += __shfl_xor_sync(0xffffffffu, cnt, o);
        float mask = (float)cnt * (1.0f / 192.0f);
        #pragma unroll
        for (int u = 0; u < 3; u++) {
            stage_hi(smem, IMG_X, p, 2 * lane + 64 * u, xv[u].x * mask, xv[u].y * mask);
            stage_hi(smem, IMG_Y, p, 2 * lane + 64 * u, yv[u].x, yv[u].y);
        }
        if (lane == 0) { s_logmw[p] = logf(mask + 1e-6f); s_goff[p] = goff; }
    }
    __syncthreads();

    // ---- GEMM q -> Q frags (reads IMG_X) ----
    run_gemm(smem, &g_Bimg[0][0][0], IMG_X, nullptr, nullptr, tx, 1);
    __syncthreads();   // IMG_X fully consumed (V writes VF there next)

    // ---- GEMM k -> K frags; GEMM v -> VF frags (both read IMG_Y; no barrier between) ----
    run_gemm(smem, &g_Bimg[1][0][0], IMG_Y, nullptr, nullptr, tx, 2);
    run_gemm(smem, &g_Bimg[2][0][0], IMG_Y, nullptr, nullptr, tx, 3);
    __syncthreads();   // QF/KF/VF complete

    // ---- fused logits -> register softmax -> att gmem -> att@v -> ctx frags ----
    {
        const int g = lane >> 2, t = lane & 3;
        for (int u = wid; u < 24; u += 12) {
            const int h = u >> 2, mt = u & 3;
            const int n0 = mt * 16 + g;
            uint4 qh0 = *(const uint4*)(smem + QF_HI + (((h * 4 + mt) * 2 + 0) * 32 + lane) * 16);
            uint4 qh1 = *(const uint4*)(smem + QF_HI + (((h * 4 + mt) * 2 + 1) * 32 + lane) * 16);
            float c[7][4];
            #pragma unroll
            for (int nt = 0; nt < 7; nt++) {
                uint2 bh0 = *(const uint2*)(smem + KF_HI + (((h * 2 + 0) * 7 + nt) * 32 + lane) * 8);
                uint2 bh1 = *(const uint2*)(smem + KF_HI + (((h * 2 + 1) * 7 + nt) * 32 + lane) * 8);
                c[nt][0] = c[nt][1] = c[nt][2] = c[nt][3] = 0.0f;
                mma16816(c[nt], (const uint32_t*)&qh0, bh0.x, bh0.y);
                mma16816(c[nt], (const uint32_t*)&qh1, bh1.x, bh1.y);
            }
            #pragma unroll
            for (int nt = 0; nt < 6; nt++) {
                float2 lm = *(const float2*)(s_logmw + 8 * nt + 2 * t);
                c[nt][0] += lm.x; c[nt][1] += lm.y;
                c[nt][2] += lm.x; c[nt][3] += lm.y;
            }
            {
                float lm48 = s_logmw[48];
                c[6][0] = (t == 0) ? c[6][0] + lm48 : -1e30f;
                c[6][2] = (t == 0) ? c[6][2] + lm48 : -1e30f;
                c[6][1] = -1e30f;  c[6][3] = -1e30f;
            }
            float mx0 = -1e30f, mx1 = -1e30f;
            #pragma unroll
            for (int nt = 0; nt < 7; nt++) {
                mx0 = fmaxf(mx0, fmaxf(c[nt][0], c[nt][1]));
                mx1 = fmaxf(mx1, fmaxf(c[nt][2], c[nt][3]));
            }
            mx0 = fmaxf(mx0, __shfl_xor_sync(0xffffffffu, mx0, 1));
            mx0 = fmaxf(mx0, __shfl_xor_sync(0xffffffffu, mx0, 2));
            mx1 = fmaxf(mx1, __shfl_xor_sync(0xffffffffu, mx1, 1));
            mx1 = fmaxf(mx1, __shfl_xor_sync(0xffffffffu, mx1, 2));
            float s0 = 0.0f, s1 = 0.0f;
            #pragma unroll
            for (int nt = 0; nt < 7; nt++) {
                c[nt][0] = __expf(c[nt][0] - mx0); s0 += c[nt][0];
                c[nt][1] = __expf(c[nt][1] - mx0); s0 += c[nt][1];
                c[nt][2] = __expf(c[nt][2] - mx1); s1 += c[nt][2];
                c[nt][3] = __expf(c[nt][3] - mx1); s1 += c[nt][3];
            }
            s0 += __shfl_xor_sync(0xffffffffu, s0, 1);
            s0 += __shfl_xor_sync(0xffffffffu, s0, 2);
            s1 += __shfl_xor_sync(0xffffffffu, s1, 1);
            s1 += __shfl_xor_sync(0xffffffffu, s1, 2);
            float inv0 = 1.0f / s0, inv1 = 1.0f / s1;
            #pragma unroll
            for (int nt = 0; nt < 7; nt++) {
                c[nt][0] *= inv0; c[nt][1] *= inv0;
                c[nt][2] *= inv1; c[nt][3] *= inv1;
            }
            {
                float* ab = att_out + (size_t)w * ATT_W + h * 2401;
                #pragma unroll
                for (int nt = 0; nt < 7; nt++) {
                    int m0 = 8 * nt + 2 * t;
                    if (n0 < NPIX) {
                        if (m0     < NPIX) ab[n0 * NPIX + m0]     = c[nt][0];
                        if (m0 + 1 < NPIX) ab[n0 * NPIX + m0 + 1] = c[nt][1];
                    }
                    if (n0 + 8 < NPIX) {
                        if (m0     < NPIX) ab[(n0 + 8) * NPIX + m0]     = c[nt][2];
                        if (m0 + 1 < NPIX) ab[(n0 + 8) * NPIX + m0 + 1] = c[nt][3];
                    }
                }
            }
            // att@v via mma (1-pass)
            float d[4][4];
            #pragma unroll
            for (int n2 = 0; n2 < 4; n2++)
                d[n2][0] = d[n2][1] = d[n2][2] = d[n2][3] = 0.0f;
            #pragma unroll
            for (int kt = 0; kt < 4; kt++) {
                uint32_t Ah[4];
                Ah[0] = cvt2(c[2*kt][0], c[2*kt][1]);
                Ah[1] = cvt2(c[2*kt][2], c[2*kt][3]);
                if (2 * kt + 1 < 7) {
                    Ah[2] = cvt2(c[2*kt+1][0], c[2*kt+1][1]);
                    Ah[3] = cvt2(c[2*kt+1][2], c[2*kt+1][3]);
                } else {
                    Ah[2] = Ah[3] = 0u;
                }
                #pragma unroll
                for (int n2 = 0; n2 < 4; n2++) {
                    uint2 bh = *(const uint2*)(smem + VF_HI + (((h * 4 + kt) * 4 + n2) * 32 + lane) * 8);
                    mma16816(d[n2], Ah, bh.x, bh.y);
                }
            }
            // ctx -> A-fragment image (hi only) for GEMM o
            #pragma unroll
            for (int n2 = 0; n2 < 4; n2++) {
                uint32_t h0 = cvt2(d[n2][0], d[n2][1]);
                uint32_t h1 = cvt2(d[n2][2], d[n2][3]);
                int kt_o = 2 * h + (n2 >> 1);
                int khi  = n2 & 1;
                int off  = ((kt_o * 4 + mt) * 32 + lane) * 16 + khi * 8;
                *(uint2*)(smem + CTX_OFF + off) = make_uint2(h0, h1);
            }
        }
    }
    __syncthreads();

    // ---- GEMM o (A = ctx frags) -> direct gmem stores ----
    run_gemm(smem, &g_Bimg[3][0][0], CTX_OFF, out, s_goff, tx, 0);
}

extern "C" void kernel_launch(void* const* d_in, const int* in_sizes, int n_in,
                              void* d_out, int out_size)
{
    const float* x  = (const float*)d_in[0];
    const float* y  = (const float*)d_in[1];
    const float* Wq = (const float*)d_in[2];
    const float* Wk = (const float*)d_in[3];
    const float* Wv = (const float*)d_in[4];
    const float* Wo = (const float*)d_in[5];

    float* out = (float*)d_out;                       // [8,224,224,192]
    float* att = out + (size_t)8 * 224 * 224 * 192;   // [8192,6,49,49]

    prep_w<<<576, 256>>>(Wq, Wk, Wv, Wo);

    cudaFuncSetAttribute(fused_winattn,
                         cudaFuncAttributeMaxDynamicSharedMemorySize, SMEM_BYTES);
    fused_winattn<<<NWIN, NTHR, SMEM_BYTES>>>(x, y, out, att);
}

// round 16
// speedup vs baseline: 1.2340x; 1.2340x over previous
#include <cuda_runtime.h>
#include <cuda_fp16.h>
#include <math.h>
#include <stdint.h>

#define HH      224
#define C_      192
#define NPIX    49
#define HEADS   6
#define NWIN    8192
#define ATT_W   14406
#define NTHR    384

// ---- smem byte layout (105.4 KB -> 2 CTAs/SM) ----
#define IMG_X   0          // x A-image (24576); VF_HI aliases after Q-GEMM
#define IMG_Y   24576      // y A-image (24576); CTX frags alias during attention
#define B_OFF   49152      // B half-chunk staging (12288)
#define QF_HI   61440      // 24576
#define KF_HI   86016      // 21504
#define LOGMW_O 107520
#define GOFF_O  107728
#define SMEM_BYTES 107936
#define VF_HI   0
#define CTX_OFF 24576

// weight images (f16 hi only) in mma-B-fragment order: [w][chunk][12288]
__device__ __align__(16) __half g_Bimg[4][3][12288];

// ---------------- helpers ----------------
__device__ __forceinline__ void mma16816(float* c, const uint32_t* a, uint32_t b0, uint32_t b1) {
    asm volatile("mma.sync.aligned.m16n8k16.row.col.f32.f16.f16.f32 "
        "{%0,%1,%2,%3}, {%4,%5,%6,%7}, {%8,%9}, {%0,%1,%2,%3};"
        : "+f"(c[0]), "+f"(c[1]), "+f"(c[2]), "+f"(c[3])
        : "r"(a[0]), "r"(a[1]), "r"(a[2]), "r"(a[3]), "r"(b0), "r"(b1));
}
__device__ __forceinline__ uint32_t cvt2(float a, float b) {
    __half2 h2 = __float22half2_rn(make_float2(a, b));
    return *(uint32_t*)&h2;
}
__device__ __forceinline__ void stcs1(float* p, float v) {
    asm volatile("st.global.cs.f32 [%0], %1;" :: "l"(p), "f"(v) : "memory");
}
__device__ __forceinline__ void stcs2(float* p, float2 v) {
    asm volatile("st.global.cs.v2.f32 [%0], {%1,%2};" :: "l"(p), "f"(v.x), "f"(v.y) : "memory");
}

// ---------------- prep: weights -> f16 fragment-order images (hi only) ----------------
__global__ void prep_w(const float* __restrict__ Wq, const float* __restrict__ Wk,
                       const float* __restrict__ Wv, const float* __restrict__ Wo)
{
    int e = blockIdx.x * 256 + threadIdx.x;
    if (e >= 4 * 36864) return;
    int wsel = e / 36864, r = e % 36864;
    int k = r / 192, n = r % 192;
    const float* W = (wsel == 0) ? Wq : (wsel == 1) ? Wk : (wsel == 2) ? Wv : Wo;
    __half h = __float2half_rn(W[k * 192 + n]);
    int chunk = k >> 6, kk = k & 63;
    int kt = kk >> 4, kc = kk & 15;
    int khi = kc >> 3, t = (kc & 7) >> 1, half = kc & 1;
    int ntile = n >> 3, g = n & 7;
    int lane = g * 4 + t;
    int off = ((kt * 24 + ntile) * 32 + lane) * 4 + khi * 2 + half;
    g_Bimg[wsel][chunk][off] = h;
}

// stage A element pair (hi only) into fragment-order image at base
__device__ __forceinline__ void stage_hi(char* smem, int base, int p, int c, float a0, float a1)
{
    uint32_t hi = cvt2(a0, a1);
    int mt = p >> 4, rr = p & 15;
    int g = rr & 7, hi8 = rr >> 3;
    int kt = c >> 4, cc = c & 15;
    int khi = cc >> 3, t = (cc & 7) >> 1;
    int reg = hi8 + 2 * khi;
    int off = (((kt * 4 + mt) * 32 + g * 4 + t) * 8 + reg * 2) * 2;
    *(uint32_t*)(smem + base + off) = hi;
}

// ---- 12-warp GEMM, 1-pass, 2mt x 4j per warp, 6 half-chunk B stages (smem staged).
// mode: 0 = direct gmem out (O), 1 = Q frags (scaled), 2 = K frags, 3 = VF frags (V)
__device__ void run_gemm(char* smem, const __half* img, int a_base,
                         float* __restrict__ gout, const int* s_goff,
                         int tx, int mode, uint4* wreg)
{
    const int wid = tx >> 5, lane = tx & 31;
    const int mp = wid >= 6, jg = wid - 6 * mp;   // mp in {0,1}, jg in {0..5}
    const int g = lane >> 2, t = lane & 3;

    float c[2][4][4];
    #pragma unroll
    for (int m2 = 0; m2 < 2; m2++)
        #pragma unroll
        for (int jj = 0; jj < 4; jj++)
            #pragma unroll
            for (int i = 0; i < 4; i++) c[m2][jj][i] = 0.0f;

    for (int hs = 0; hs < 6; hs++) {
        __syncthreads();
        uint4* bb = (uint4*)(smem + B_OFF);
        #pragma unroll
        for (int i = 0; i < 2; i++) bb[tx + NTHR * i] = wreg[i];
        __syncthreads();
        if (hs < 5) {
            const uint4* nsrc = (const uint4*)(img + (hs + 1) * 6144);
            #pragma unroll
            for (int i = 0; i < 2; i++) wreg[i] = nsrc[tx + NTHR * i];
        }
        #pragma unroll
        for (int ktl = 0; ktl < 2; ktl++) {
            const int kt = hs * 2 + ktl;
            uint4 ah[2];
            #pragma unroll
            for (int m2 = 0; m2 < 2; m2++)
                ah[m2] = *(const uint4*)(smem + a_base + ((kt * 4 + 2 * mp + m2) * 32 + lane) * 16);
            #pragma unroll
            for (int jj = 0; jj < 4; jj++) {
                const int j = jg * 4 + jj;
                uint2 b = *(const uint2*)(smem + B_OFF + ((ktl * 24 + j) * 32 + lane) * 8);
                mma16816(c[0][jj], (const uint32_t*)&ah[0], b.x, b.y);
                mma16816(c[1][jj], (const uint32_t*)&ah[1], b.x, b.y);
            }
        }
    }
    __syncthreads();

    if (mode == 0) {
        // O: store straight to gmem (roll-back == gather map). goff%192==0, col even -> 8B aligned.
        #pragma unroll
        for (int m2 = 0; m2 < 2; m2++) {
            const int mt = 2 * mp + m2;
            const int r0 = mt * 16 + g, r1 = r0 + 8;
            int o0 = (r0 < NPIX) ? s_goff[r0] : 0;
            int o1 = (r1 < NPIX) ? s_goff[r1] : 0;
            #pragma unroll
            for (int jj = 0; jj < 4; jj++) {
                int col = (jg * 4 + jj) * 8 + 2 * t;
                if (r0 < NPIX) stcs2(gout + o0 + col, make_float2(c[m2][jj][0], c[m2][jj][1]));
                if (r1 < NPIX) stcs2(gout + o1 + col, make_float2(c[m2][jj][2], c[m2][jj][3]));
            }
        }
    } else if (mode == 1) {
        // Q: scale -> A-fragment image. h = jg; kb in {0,1}.
        const float SCALE = 0.17677669529663687f;
        #pragma unroll
        for (int m2 = 0; m2 < 2; m2++) {
            const int mt = 2 * mp + m2;
            #pragma unroll
            for (int kb = 0; kb < 2; kb++) {
                uint32_t w0 = cvt2(c[m2][2*kb][0]*SCALE,   c[m2][2*kb][1]*SCALE);
                uint32_t w1 = cvt2(c[m2][2*kb][2]*SCALE,   c[m2][2*kb][3]*SCALE);
                uint32_t w2 = cvt2(c[m2][2*kb+1][0]*SCALE, c[m2][2*kb+1][1]*SCALE);
                uint32_t w3 = cvt2(c[m2][2*kb+1][2]*SCALE, c[m2][2*kb+1][3]*SCALE);
                int off = (((jg * 4 + mt) * 2 + kb) * 32 + lane) * 16;
                *(uint4*)(smem + QF_HI + off) = make_uint4(w0, w1, w2, w3);
            }
        }
    } else if (mode == 2) {
        // K -> B-fragment image, packed uint2 (khi pair). h = jg. Guard nt=2mt+1<7.
        #pragma unroll
        for (int m2 = 0; m2 < 2; m2++) {
            const int mt = 2 * mp + m2;
            #pragma unroll
            for (int kb = 0; kb < 2; kb++) {
                uint32_t a0 = cvt2(c[m2][2*kb][0],   c[m2][2*kb][1]);    // khi=0, nt=2mt
                uint32_t b0 = cvt2(c[m2][2*kb+1][0], c[m2][2*kb+1][1]);  // khi=1, nt=2mt
                uint32_t a1 = cvt2(c[m2][2*kb][2],   c[m2][2*kb][3]);    // khi=0, nt=2mt+1
                uint32_t b1 = cvt2(c[m2][2*kb+1][2], c[m2][2*kb+1][3]);  // khi=1, nt=2mt+1
                int base0 = (((jg * 2 + kb) * 7 + 2 * mt) * 32 + lane) * 8;
                *(uint2*)(smem + KF_HI + base0) = make_uint2(a0, b0);
                if (2 * mt + 1 < 7)
                    *(uint2*)(smem + KF_HI + base0 + 256) = make_uint2(a1, b1);
            }
        }
    } else {
        // V: direct B-fragment store. Lane pairing rows (g, g^1) via shfl_xor lane^4.
        const int even = !(g & 1);
        const int tt = g >> 1;
        #pragma unroll
        for (int m2 = 0; m2 < 2; m2++) {
            const int mt = 2 * mp + m2;
            #pragma unroll
            for (int jj = 0; jj < 4; jj++) {
                int col = (jg * 4 + jj) * 8 + 2 * t;
                float p0 = __shfl_xor_sync(0xffffffffu, c[m2][jj][0], 4);
                float p1 = __shfl_xor_sync(0xffffffffu, c[m2][jj][1], 4);
                float p2 = __shfl_xor_sync(0xffffffffu, c[m2][jj][2], 4);
                float p3 = __shfl_xor_sync(0xffffffffu, c[m2][jj][3], 4);
                int m0 = 16 * mt + (even ? g : g - 1);
                float va0 = even ? c[m2][jj][0] : p1;
                float vb0 = even ? p0 : c[m2][jj][1];
                float va1 = even ? c[m2][jj][2] : p3;
                float vb1 = even ? p2 : c[m2][jj][3];
                va0 = (m0     < NPIX) ? va0 : 0.0f;
                vb0 = (m0 + 1 < NPIX) ? vb0 : 0.0f;
                va1 = (m0 + 8 < NPIX) ? va1 : 0.0f;
                vb1 = (m0 + 9 < NPIX) ? vb1 : 0.0f;
                int ch = col + (even ? 0 : 1);
                uint32_t h0 = cvt2(va0, vb0);
                uint32_t h1 = cvt2(va1, vb1);
                int hh = ch >> 5, nt2 = (ch >> 3) & 3, gg = ch & 7;
                int id = ((hh * 4 + mt) * 4 + nt2) * 32 + gg * 4 + tt;
                *(uint2*)(smem + VF_HI + id * 8) = make_uint2(h0, h1);
            }
        }
    }
}

__global__ __launch_bounds__(NTHR, 2)
void fused_winattn(const float* __restrict__ x, const float* __restrict__ y,
                   float* __restrict__ out, float* __restrict__ att_out)
{
    extern __shared__ __align__(16) char smem[];
    float* s_logmw = (float*)(smem + LOGMW_O);
    int*   s_goff  = (int*)(smem + GOFF_O);

    const int tx = threadIdx.x;
    const int wid = tx >> 5, lane = tx & 31;
    const int w  = blockIdx.x;
    const int b  = w >> 10;
    const int wr = (w >> 5) & 31;
    const int wc = w & 31;

    // ---- prefetch Q's B half-chunk 0 (hidden under gather) ----
    uint4 wreg[2];
    {
        const uint4* s0 = (const uint4*)&g_Bimg[0][0][0];
        wreg[0] = s0[tx];
        wreg[1] = s0[tx + NTHR];
    }

    // ---- gather x (roll + mask) AND y -> A-images; logmw, goff ----
    for (int p = wid; p < NPIX; p += 12) {
        int i = p / 7, j = p - i * 7;
        int hs = wr * 7 + i + 3;  if (hs >= HH) hs -= HH;
        int vs = wc * 7 + j + 3;  if (vs >= HH) vs -= HH;
        int goff = ((b * HH + hs) * HH + vs) * C_;
        float2 xv[3], yv[3];
        int cnt = 0;
        #pragma unroll
        for (int u = 0; u < 3; u++) {
            xv[u] = *(const float2*)(x + goff + 2 * lane + 64 * u);
            yv[u] = *(const float2*)(y + goff + 2 * lane + 64 * u);
            cnt += (xv[u].x > 0.95f ? 0 : 1) + (xv[u].y > 0.95f ? 0 : 1);
        }
        #pragma unroll
        for (int o = 16; o; o >>= 1) cnt += __shfl_xor_sync(0xffffffffu, cnt, o);
        float mask = (float)cnt * (1.0f / 192.0f);
        #pragma unroll
        for (int u = 0; u < 3; u++) {
            stage_hi(smem, IMG_X, p, 2 * lane + 64 * u, xv[u].x * mask, xv[u].y * mask);
            stage_hi(smem, IMG_Y, p, 2 * lane + 64 * u, yv[u].x, yv[u].y);
        }
        if (lane == 0) { s_logmw[p] = logf(mask + 1e-6f); s_goff[p] = goff; }
    }
    __syncthreads();

    // ---- GEMM q -> Q frags ----
    run_gemm(smem, &g_Bimg[0][0][0], IMG_X, nullptr, nullptr, tx, 1, wreg);
    wreg[0] = ((const uint4*)&g_Bimg[1][0][0])[tx];
    wreg[1] = ((const uint4*)&g_Bimg[1][0][0])[tx + NTHR];

    // ---- GEMM k -> K frags ----
    run_gemm(smem, &g_Bimg[1][0][0], IMG_Y, nullptr, nullptr, tx, 2, wreg);
    wreg[0] = ((const uint4*)&g_Bimg[2][0][0])[tx];
    wreg[1] = ((const uint4*)&g_Bimg[2][0][0])[tx + NTHR];

    // ---- GEMM v -> VF frags (into IMG_X region; x-image dead) ----
    run_gemm(smem, &g_Bimg[2][0][0], IMG_Y, nullptr, nullptr, tx, 3, wreg);
    __syncthreads();

    // ---- fused logits -> register softmax -> att gmem -> att@v -> ctx frags ----
    {
        const int g = lane >> 2, t = lane & 3;
        for (int u = wid; u < 24; u += 12) {
            const int h = u >> 2, mt = u & 3;
            const int n0 = mt * 16 + g;
            uint4 qh0 = *(const uint4*)(smem + QF_HI + (((h * 4 + mt) * 2 + 0) * 32 + lane) * 16);
            uint4 qh1 = *(const uint4*)(smem + QF_HI + (((h * 4 + mt) * 2 + 1) * 32 + lane) * 16);
            float c[7][4];
            #pragma unroll
            for (int nt = 0; nt < 7; nt++) {
                uint2 bh0 = *(const uint2*)(smem + KF_HI + (((h * 2 + 0) * 7 + nt) * 32 + lane) * 8);
                uint2 bh1 = *(const uint2*)(smem + KF_HI + (((h * 2 + 1) * 7 + nt) * 32 + lane) * 8);
                c[nt][0] = c[nt][1] = c[nt][2] = c[nt][3] = 0.0f;
                mma16816(c[nt], (const uint32_t*)&qh0, bh0.x, bh0.y);
                mma16816(c[nt], (const uint32_t*)&qh1, bh1.x, bh1.y);
            }
            #pragma unroll
            for (int nt = 0; nt < 6; nt++) {
                float2 lm = *(const float2*)(s_logmw + 8 * nt + 2 * t);
                c[nt][0] += lm.x; c[nt][1] += lm.y;
                c[nt][2] += lm.x; c[nt][3] += lm.y;
            }
            {
                float lm48 = s_logmw[48];
                c[6][0] = (t == 0) ? c[6][0] + lm48 : -1e30f;
                c[6][2] = (t == 0) ? c[6][2] + lm48 : -1e30f;
                c[6][1] = -1e30f;  c[6][3] = -1e30f;
            }
            float mx0 = -1e30f, mx1 = -1e30f;
            #pragma unroll
            for (int nt = 0; nt < 7; nt++) {
                mx0 = fmaxf(mx0, fmaxf(c[nt][0], c[nt][1]));
                mx1 = fmaxf(mx1, fmaxf(c[nt][2], c[nt][3]));
            }
            mx0 = fmaxf(mx0, __shfl_xor_sync(0xffffffffu, mx0, 1));
            mx0 = fmaxf(mx0, __shfl_xor_sync(0xffffffffu, mx0, 2));
            mx1 = fmaxf(mx1, __shfl_xor_sync(0xffffffffu, mx1, 1));
            mx1 = fmaxf(mx1, __shfl_xor_sync(0xffffffffu, mx1, 2));
            float s0 = 0.0f, s1 = 0.0f;
            #pragma unroll
            for (int nt = 0; nt < 7; nt++) {
                c[nt][0] = __expf(c[nt][0] - mx0); s0 += c[nt][0];
                c[nt][1] = __expf(c[nt][1] - mx0); s0 += c[nt][1];
                c[nt][2] = __expf(c[nt][2] - mx1); s1 += c[nt][2];
                c[nt][3] = __expf(c[nt][3] - mx1); s1 += c[nt][3];
            }
            s0 += __shfl_xor_sync(0xffffffffu, s0, 1);
            s0 += __shfl_xor_sync(0xffffffffu, s0, 2);
            s1 += __shfl_xor_sync(0xffffffffu, s1, 1);
            s1 += __shfl_xor_sync(0xffffffffu, s1, 2);
            float inv0 = 1.0f / s0, inv1 = 1.0f / s1;
            #pragma unroll
            for (int nt = 0; nt < 7; nt++) {
                c[nt][0] *= inv0; c[nt][1] *= inv0;
                c[nt][2] *= inv1; c[nt][3] *= inv1;
            }
            {
                float* ab = att_out + (size_t)w * ATT_W + h * 2401;
                #pragma unroll
                for (int nt = 0; nt < 7; nt++) {
                    int m0 = 8 * nt + 2 * t;
                    if (n0 < NPIX) {
                        if (m0     < NPIX) stcs1(ab + n0 * NPIX + m0,     c[nt][0]);
                        if (m0 + 1 < NPIX) stcs1(ab + n0 * NPIX + m0 + 1, c[nt][1]);
                    }
                    if (n0 + 8 < NPIX) {
                        if (m0     < NPIX) stcs1(ab + (n0 + 8) * NPIX + m0,     c[nt][2]);
                        if (m0 + 1 < NPIX) stcs1(ab + (n0 + 8) * NPIX + m0 + 1, c[nt][3]);
                    }
                }
            }
            // att@v via mma (1-pass)
            float d[4][4];
            #pragma unroll
            for (int n2 = 0; n2 < 4; n2++)
                d[n2][0] = d[n2][1] = d[n2][2] = d[n2][3] = 0.0f;
            #pragma unroll
            for (int kt = 0; kt < 4; kt++) {
                uint32_t Ah[4];
                Ah[0] = cvt2(c[2*kt][0], c[2*kt][1]);
                Ah[1] = cvt2(c[2*kt][2], c[2*kt][3]);
                if (2 * kt + 1 < 7) {
                    Ah[2] = cvt2(c[2*kt+1][0], c[2*kt+1][1]);
                    Ah[3] = cvt2(c[2*kt+1][2], c[2*kt+1][3]);
                } else {
                    Ah[2] = Ah[3] = 0u;
                }
                #pragma unroll
                for (int n2 = 0; n2 < 4; n2++) {
                    uint2 bh = *(const uint2*)(smem + VF_HI + (((h * 4 + kt) * 4 + n2) * 32 + lane) * 8);
                    mma16816(d[n2], Ah, bh.x, bh.y);
                }
            }
            // ctx -> A-fragment image (hi only) for GEMM o
            #pragma unroll
            for (int n2 = 0; n2 < 4; n2++) {
                uint32_t h0 = cvt2(d[n2][0], d[n2][1]);
                uint32_t h1 = cvt2(d[n2][2], d[n2][3]);
                int kt_o = 2 * h + (n2 >> 1);
                int khi  = n2 & 1;
                int off  = ((kt_o * 4 + mt) * 32 + lane) * 16 + khi * 8;
                *(uint2*)(smem + CTX_OFF + off) = make_uint2(h0, h1);
            }
        }
    }
    __syncthreads();

    // ---- GEMM o (A = ctx frags) -> direct gmem stores ----
    wreg[0] = ((const uint4*)&g_Bimg[3][0][0])[tx];
    wreg[1] = ((const uint4*)&g_Bimg[3][0][0])[tx + NTHR];
    run_gemm(smem, &g_Bimg[3][0][0], CTX_OFF, out, s_goff, tx, 0, wreg);
}

extern "C" void kernel_launch(void* const* d_in, const int* in_sizes, int n_in,
                              void* d_out, int out_size)
{
    const float* x  = (const float*)d_in[0];
    const float* y  = (const float*)d_in[1];
    const float* Wq = (const float*)d_in[2];
    const float* Wk = (const float*)d_in[3];
    const float* Wv = (const float*)d_in[4];
    const float* Wo = (const float*)d_in[5];

    float* out = (float*)d_out;                       // [8,224,224,192]
    float* att = out + (size_t)8 * 224 * 224 * 192;   // [8192,6,49,49]

    prep_w<<<576, 256>>>(Wq, Wk, Wv, Wo);

    cudaFuncSetAttribute(fused_winattn,
                         cudaFuncAttributeMaxDynamicSharedMemorySize, SMEM_BYTES);
    fused_winattn<<<NWIN, NTHR, SMEM_BYTES>>>(x, y, out, att);
}